// round 2
// baseline (speedup 1.0000x reference)
#include <cuda_runtime.h>
#include <math.h>

#define SEQN 320
#define HN   400
#define G4   1600   // 4*H
#define BI2  800    // 2*H
#define NOUT 321

// ------------------------- scratch (device globals; no allocation) -------------------------
__device__ float g_x[SEQN * HN];        // embedded input  [320,400]
__device__ float g_projf[SEQN * G4];    // input projections (reused per layer)
__device__ float g_projb[SEQN * G4];
__device__ float g_out0[SEQN * BI2];    // layer0 bilstm output
__device__ float g_hv[SEQN * BI2];      // layer1 bilstm output
__device__ float g_A[SEQN * G4];        // hv @ w1a^T + b1
__device__ float g_B[SEQN * G4];        // hv @ w1b^T
__device__ float g_h[2][2][HN];         // [dir][parity][h]
__device__ unsigned g_cnt[2];
__device__ volatile unsigned g_epoch[2];

// ------------------------- embed -------------------------
__global__ void embed_k(const int* __restrict__ words, const int* __restrict__ tags,
                        const float* __restrict__ wemb, const float* __restrict__ temb) {
    int t = blockIdx.x;
    int w = words[t], tg = tags[t];
    for (int d = threadIdx.x; d < 300; d += blockDim.x) g_x[t * HN + d] = wemb[w * 300 + d];
    for (int d = threadIdx.x; d < 100; d += blockDim.x) g_x[t * HN + 300 + d] = temb[tg * 100 + d];
}

// ------------------------- GEMM: C[M,N] = X[M,K] * W[N,K]^T + bias1 + bias2 -------------------------
// X contiguous with row stride K. W row stride = ldw. M=320, N=1600 always here; K in {400,800}; all %16==0.
#define BM 64
#define BN 64
#define BKK 16

__global__ void __launch_bounds__(256) gemm_tn(float* __restrict__ C,
    const float* __restrict__ X, const float* __restrict__ W,
    const float* __restrict__ bias1, const float* __restrict__ bias2,
    int N, int K, int ldw)
{
    __shared__ float Xs[BKK][BM + 4];
    __shared__ float Ws[BKK][BN + 4];
    int tid = threadIdx.x;
    int m0 = blockIdx.y * BM, n0 = blockIdx.x * BN;
    int lr = tid >> 2, seg = tid & 3;                 // load mapping: 64 rows x 4 float4-segs
    const float* xp = X + (size_t)(m0 + lr) * K + seg * 4;
    const float* wp = W + (size_t)(n0 + lr) * ldw + seg * 4;
    int ty = tid >> 4, tx = tid & 15;                 // compute mapping: 16x16, 4x4 micro
    float acc[4][4];
#pragma unroll
    for (int i = 0; i < 4; ++i)
#pragma unroll
        for (int j = 0; j < 4; ++j) acc[i][j] = 0.f;

    int nt = K / BKK;
    float4 xa = *(const float4*)xp;
    float4 wa = *(const float4*)wp;
    for (int kt = 0; kt < nt; ++kt) {
        __syncthreads();
        Xs[seg * 4 + 0][lr] = xa.x; Xs[seg * 4 + 1][lr] = xa.y;
        Xs[seg * 4 + 2][lr] = xa.z; Xs[seg * 4 + 3][lr] = xa.w;
        Ws[seg * 4 + 0][lr] = wa.x; Ws[seg * 4 + 1][lr] = wa.y;
        Ws[seg * 4 + 2][lr] = wa.z; Ws[seg * 4 + 3][lr] = wa.w;
        __syncthreads();
        if (kt + 1 < nt) {
            xa = *(const float4*)(xp + (kt + 1) * BKK);
            wa = *(const float4*)(wp + (kt + 1) * BKK);
        }
#pragma unroll
        for (int kk = 0; kk < BKK; ++kk) {
            float4 a = *(const float4*)&Xs[kk][ty * 4];
            float4 b = *(const float4*)&Ws[kk][tx * 4];
            float av[4] = {a.x, a.y, a.z, a.w};
            float bv[4] = {b.x, b.y, b.z, b.w};
#pragma unroll
            for (int i = 0; i < 4; ++i)
#pragma unroll
                for (int j = 0; j < 4; ++j)
                    acc[i][j] = fmaf(av[i], bv[j], acc[i][j]);
        }
    }
    float bb[4] = {0.f, 0.f, 0.f, 0.f};
    if (bias1) {
#pragma unroll
        for (int j = 0; j < 4; ++j) bb[j] += bias1[n0 + tx * 4 + j];
    }
    if (bias2) {
#pragma unroll
        for (int j = 0; j < 4; ++j) bb[j] += bias2[n0 + tx * 4 + j];
    }
#pragma unroll
    for (int i = 0; i < 4; ++i) {
        float4 o;
        o.x = acc[i][0] + bb[0]; o.y = acc[i][1] + bb[1];
        o.z = acc[i][2] + bb[2]; o.w = acc[i][3] + bb[3];
        *(float4*)(C + (size_t)(m0 + ty * 4 + i) * N + n0 + tx * 4) = o;
    }
}

// ------------------------- recurrent scan (both directions, persistent, grid barrier) -------------------------
// 50 blocks/dir * 8 hidden-elems/block. Warp = col-segment (50 h values), lane = gate-row (4 gates x 8 hidden).
// W_hh slice lives entirely in registers (50 fp32/thread).
#define NBD  50
#define HB   8
#define CSEG 50

__device__ __forceinline__ void bar_sync(int dir) {
    __syncthreads();
    if (threadIdx.x == 0) {
        __threadfence();
        unsigned e = g_epoch[dir];
        unsigned old = atomicAdd(&g_cnt[dir], 1u);
        if (old == NBD - 1) {
            g_cnt[dir] = 0;
            __threadfence();
            g_epoch[dir] = e + 1;
        } else {
            while (g_epoch[dir] == e) { }
        }
        __threadfence();
    }
    __syncthreads();
}

__global__ void __launch_bounds__(256) scan_k(
    float* __restrict__ outp,
    const float* __restrict__ projf, const float* __restrict__ projb,
    const float* __restrict__ whhf, const float* __restrict__ whhb,
    const float* __restrict__ h0, const float* __restrict__ c0, int layer)
{
    int dir  = blockIdx.x / NBD;
    int blk  = blockIdx.x % NBD;
    int k0   = blk * HB;
    int tid  = threadIdx.x;
    int lane = tid & 31;
    int warp = tid >> 5;        // 0..7 col-segment
    int gate = lane >> 3;       // 0..3 (i,f,g,o)
    int hloc = lane & 7;        // 0..7 hidden within block
    int row  = gate * HN + k0 + hloc;   // W_hh / proj row

    const float* whh  = dir ? whhb : whhf;
    const float* proj = dir ? projb : projf;

    __shared__ float hs[HN];
    __shared__ float psum[32 * 9];
    __shared__ float cs[HB];

    float w[CSEG];
    const float* wrow = whh + (size_t)row * HN + warp * CSEG;
#pragma unroll
    for (int c = 0; c < CSEG; ++c) w[c] = wrow[c];

    if (tid < HB) {
        cs[tid] = c0[(2 * layer + dir) * HN + k0 + tid];
        g_h[dir][0][k0 + tid] = h0[(2 * layer + dir) * HN + k0 + tid];
    }
    bar_sync(dir);

    for (int t = 0; t < SEQN; ++t) {
        int par = t & 1;
        for (int i = tid; i < HN; i += 256) hs[i] = __ldcg(&g_h[dir][par][i]);
        __syncthreads();

        float acc = 0.f;
        const float* hseg = &hs[warp * CSEG];
#pragma unroll
        for (int c = 0; c < CSEG; ++c) acc = fmaf(w[c], hseg[c], acc);
        psum[lane * 9 + warp] = acc;
        __syncthreads();

        if (warp == 0) {
            float s = 0.f;
#pragma unroll
            for (int c = 0; c < 8; ++c) s += psum[lane * 9 + c];
            int tt = dir ? (SEQN - 1 - t) : t;
            s += __ldg(&proj[(size_t)tt * G4 + row]);
            float iv = __shfl_sync(0xffffffffu, s, hloc);
            float fv = __shfl_sync(0xffffffffu, s, 8 + hloc);
            float gv = __shfl_sync(0xffffffffu, s, 16 + hloc);
            float ov = __shfl_sync(0xffffffffu, s, 24 + hloc);
            if (lane < HB) {
                float ig = 1.f / (1.f + expf(-iv));
                float fg = 1.f / (1.f + expf(-fv));
                float og = 1.f / (1.f + expf(-ov));
                float gc = tanhf(gv);
                float cn = fmaf(fg, cs[lane], ig * gc);
                cs[lane] = cn;
                float hn = og * tanhf(cn);
                g_h[dir][par ^ 1][k0 + lane] = hn;
                outp[(size_t)tt * BI2 + dir * HN + k0 + lane] = hn;
            }
        }
        bar_sync(dir);
    }
}

// ------------------------- pairwise scorer -------------------------
// scores[i][j] = sum_k relu(A[i,k] + B[j,k]) * w2[k] + b2 ; diag forced 0 ; write to out[(i+1),(j+1)]
#define PKC 32

__global__ void __launch_bounds__(256) pairwise_k(float* __restrict__ out,
    const float* __restrict__ A, const float* __restrict__ Bm,
    const float* __restrict__ w2, const float* __restrict__ b2p)
{
    __shared__ float As[32][PKC + 1];
    __shared__ float Bs[32][PKC + 1];
    __shared__ float ws[PKC];
    int tid = threadIdx.x;
    int i0 = blockIdx.y * 32, j0 = blockIdx.x * 32;
    int tx = tid & 15, ty = tid >> 4;
    int lr = tid >> 3, seg = tid & 7;
    float acc[2][2] = {{0.f, 0.f}, {0.f, 0.f}};

    for (int kc = 0; kc < G4; kc += PKC) {
        __syncthreads();
        float4 av = *(const float4*)(A  + (size_t)(i0 + lr) * G4 + kc + seg * 4);
        float4 bv = *(const float4*)(Bm + (size_t)(j0 + lr) * G4 + kc + seg * 4);
        As[lr][seg * 4 + 0] = av.x; As[lr][seg * 4 + 1] = av.y;
        As[lr][seg * 4 + 2] = av.z; As[lr][seg * 4 + 3] = av.w;
        Bs[lr][seg * 4 + 0] = bv.x; Bs[lr][seg * 4 + 1] = bv.y;
        Bs[lr][seg * 4 + 2] = bv.z; Bs[lr][seg * 4 + 3] = bv.w;
        if (tid < PKC) ws[tid] = w2[kc + tid];
        __syncthreads();
#pragma unroll
        for (int kk = 0; kk < PKC; ++kk) {
            float a0 = As[ty * 2 + 0][kk];
            float a1 = As[ty * 2 + 1][kk];
            float b0 = Bs[tx * 2 + 0][kk];
            float b1 = Bs[tx * 2 + 1][kk];
            float wv = ws[kk];
            acc[0][0] = fmaf(fmaxf(a0 + b0, 0.f), wv, acc[0][0]);
            acc[0][1] = fmaf(fmaxf(a0 + b1, 0.f), wv, acc[0][1]);
            acc[1][0] = fmaf(fmaxf(a1 + b0, 0.f), wv, acc[1][0]);
            acc[1][1] = fmaf(fmaxf(a1 + b1, 0.f), wv, acc[1][1]);
        }
    }
    float b2v = b2p[0];
#pragma unroll
    for (int a = 0; a < 2; ++a)
#pragma unroll
        for (int b = 0; b < 2; ++b) {
            int i = i0 + ty * 2 + a;
            int j = j0 + tx * 2 + b;
            float v = acc[a][b] + b2v;
            if (i == j) v = 0.f;
            out[(size_t)(i + 1) * NOUT + (j + 1)] = v;
        }
}

// ------------------------- border (row 0 / col 0) -------------------------
__global__ void border_k(float* __restrict__ out) {
    int i = blockIdx.x * blockDim.x + threadIdx.x;
    if (i < NOUT) {
        out[i] = (i == 0) ? 1.f : 0.f;           // row 0
        out[(size_t)i * NOUT] = (i == 0) ? 1.f : 0.f; // col 0
    }
}

// ------------------------- launch -------------------------
extern "C" void kernel_launch(void* const* d_in, const int* in_sizes, int n_in,
                              void* d_out, int out_size) {
    const int*   words   = (const int*)d_in[0];
    const int*   tags    = (const int*)d_in[1];
    // d_in[2] = arcs (unused by reference)
    const float* wemb    = (const float*)d_in[3];
    const float* temb    = (const float*)d_in[4];
    const float* h0      = (const float*)d_in[5];
    const float* c0      = (const float*)d_in[6];
    const float* w_ih_l0 = (const float*)d_in[7];
    const float* w_hh_l0 = (const float*)d_in[8];
    const float* b_ih_l0 = (const float*)d_in[9];
    const float* b_hh_l0 = (const float*)d_in[10];
    const float* w_ih_l0r= (const float*)d_in[11];
    const float* w_hh_l0r= (const float*)d_in[12];
    const float* b_ih_l0r= (const float*)d_in[13];
    const float* b_hh_l0r= (const float*)d_in[14];
    const float* w_ih_l1 = (const float*)d_in[15];
    const float* w_hh_l1 = (const float*)d_in[16];
    const float* b_ih_l1 = (const float*)d_in[17];
    const float* b_hh_l1 = (const float*)d_in[18];
    const float* w_ih_l1r= (const float*)d_in[19];
    const float* w_hh_l1r= (const float*)d_in[20];
    const float* b_ih_l1r= (const float*)d_in[21];
    const float* b_hh_l1r= (const float*)d_in[22];
    const float* mlp_w1  = (const float*)d_in[23];
    const float* mlp_b1  = (const float*)d_in[24];
    const float* mlp_w2  = (const float*)d_in[25];
    const float* mlp_b2  = (const float*)d_in[26];
    float* out = (float*)d_out;

    float *px, *ppf, *ppb, *po0, *phv, *pA, *pB;
    cudaGetSymbolAddress((void**)&px,  g_x);
    cudaGetSymbolAddress((void**)&ppf, g_projf);
    cudaGetSymbolAddress((void**)&ppb, g_projb);
    cudaGetSymbolAddress((void**)&po0, g_out0);
    cudaGetSymbolAddress((void**)&phv, g_hv);
    cudaGetSymbolAddress((void**)&pA,  g_A);
    cudaGetSymbolAddress((void**)&pB,  g_B);

    dim3 gg(G4 / BN, SEQN / BM);   // (25, 5)

    embed_k<<<SEQN, 128>>>(words, tags, wemb, temb);

    // layer 0 input projections (+ both biases folded)
    gemm_tn<<<gg, 256>>>(ppf, px, w_ih_l0,  b_ih_l0,  b_hh_l0,  G4, HN, HN);
    gemm_tn<<<gg, 256>>>(ppb, px, w_ih_l0r, b_ih_l0r, b_hh_l0r, G4, HN, HN);
    scan_k<<<2 * NBD, 256>>>(po0, ppf, ppb, w_hh_l0, w_hh_l0r, h0, c0, 0);

    // layer 1
    gemm_tn<<<gg, 256>>>(ppf, po0, w_ih_l1,  b_ih_l1,  b_hh_l1,  G4, BI2, BI2);
    gemm_tn<<<gg, 256>>>(ppb, po0, w_ih_l1r, b_ih_l1r, b_hh_l1r, G4, BI2, BI2);
    scan_k<<<2 * NBD, 256>>>(phv, ppf, ppb, w_hh_l1, w_hh_l1r, h0, c0, 1);

    // MLP halves: A = hv @ w1a^T + b1 ; B = hv @ w1b^T   (w1a/w1b are column halves of mlp_w1)
    gemm_tn<<<gg, 256>>>(pA, phv, mlp_w1,       mlp_b1, nullptr, G4, BI2, G4);
    gemm_tn<<<gg, 256>>>(pB, phv, mlp_w1 + BI2, nullptr, nullptr, G4, BI2, G4);

    border_k<<<(NOUT + 255) / 256, 256>>>(out);
    pairwise_k<<<dim3(SEQN / 32, SEQN / 32), 256>>>(out, pA, pB, mlp_w2, mlp_b2);
}

// round 7
// speedup vs baseline: 2.2202x; 2.2202x over previous
#include <cuda_runtime.h>
#include <math.h>

#define SEQN 320
#define HN   400
#define G4   1600   // 4*H
#define BI2  800    // 2*H
#define NOUT 321

// ------------------------- scratch (device globals; no allocation) -------------------------
__device__ float g_x[SEQN * HN];        // embedded input  [320,400]
__device__ float g_projf[SEQN * G4];    // input projections (reused per layer)
__device__ float g_projb[SEQN * G4];
__device__ float g_out0[SEQN * BI2];    // layer0 bilstm output
__device__ float g_hv[SEQN * BI2];      // layer1 bilstm output
__device__ float g_A[SEQN * G4];        // hv @ w1a^T + b1
__device__ float g_B[SEQN * G4];        // hv @ w1b^T

// ------------------------- embed -------------------------
__global__ void embed_k(const int* __restrict__ words, const int* __restrict__ tags,
                        const float* __restrict__ wemb, const float* __restrict__ temb) {
    int t = blockIdx.x;
    int w = words[t], tg = tags[t];
    for (int d = threadIdx.x; d < 300; d += blockDim.x) g_x[t * HN + d] = wemb[w * 300 + d];
    for (int d = threadIdx.x; d < 100; d += blockDim.x) g_x[t * HN + 300 + d] = temb[tg * 100 + d];
}

// ------------------------- GEMM: C[M,N] = X[M,K] * W[N,K]^T + bias1 + bias2 -------------------------
#define BM 64
#define BN 64
#define BKK 16

__global__ void __launch_bounds__(256) gemm_tn(float* __restrict__ C,
    const float* __restrict__ X, const float* __restrict__ W,
    const float* __restrict__ bias1, const float* __restrict__ bias2,
    int N, int K, int ldw)
{
    __shared__ float Xs[BKK][BM + 4];
    __shared__ float Ws[BKK][BN + 4];
    int tid = threadIdx.x;
    int m0 = blockIdx.y * BM, n0 = blockIdx.x * BN;
    int lr = tid >> 2, seg = tid & 3;
    const float* xp = X + (size_t)(m0 + lr) * K + seg * 4;
    const float* wp = W + (size_t)(n0 + lr) * ldw + seg * 4;
    int ty = tid >> 4, tx = tid & 15;
    float acc[4][4];
#pragma unroll
    for (int i = 0; i < 4; ++i)
#pragma unroll
        for (int j = 0; j < 4; ++j) acc[i][j] = 0.f;

    int nt = K / BKK;
    float4 xa = *(const float4*)xp;
    float4 wa = *(const float4*)wp;
    for (int kt = 0; kt < nt; ++kt) {
        __syncthreads();
        Xs[seg * 4 + 0][lr] = xa.x; Xs[seg * 4 + 1][lr] = xa.y;
        Xs[seg * 4 + 2][lr] = xa.z; Xs[seg * 4 + 3][lr] = xa.w;
        Ws[seg * 4 + 0][lr] = wa.x; Ws[seg * 4 + 1][lr] = wa.y;
        Ws[seg * 4 + 2][lr] = wa.z; Ws[seg * 4 + 3][lr] = wa.w;
        __syncthreads();
        if (kt + 1 < nt) {
            xa = *(const float4*)(xp + (kt + 1) * BKK);
            wa = *(const float4*)(wp + (kt + 1) * BKK);
        }
#pragma unroll
        for (int kk = 0; kk < BKK; ++kk) {
            float4 a = *(const float4*)&Xs[kk][ty * 4];
            float4 b = *(const float4*)&Ws[kk][tx * 4];
            float av[4] = {a.x, a.y, a.z, a.w};
            float bv[4] = {b.x, b.y, b.z, b.w};
#pragma unroll
            for (int i = 0; i < 4; ++i)
#pragma unroll
                for (int j = 0; j < 4; ++j)
                    acc[i][j] = fmaf(av[i], bv[j], acc[i][j]);
        }
    }
    float bb[4] = {0.f, 0.f, 0.f, 0.f};
    if (bias1) {
#pragma unroll
        for (int j = 0; j < 4; ++j) bb[j] += bias1[n0 + tx * 4 + j];
    }
    if (bias2) {
#pragma unroll
        for (int j = 0; j < 4; ++j) bb[j] += bias2[n0 + tx * 4 + j];
    }
#pragma unroll
    for (int i = 0; i < 4; ++i) {
        float4 o;
        o.x = acc[i][0] + bb[0]; o.y = acc[i][1] + bb[1];
        o.z = acc[i][2] + bb[2]; o.w = acc[i][3] + bb[3];
        *(float4*)(C + (size_t)(m0 + ty * 4 + i) * N + n0 + tx * 4) = o;
    }
}

// ------------------------- recurrent scan: cluster version -------------------------
// 2 clusters (fwd, bwd) of 16 CTAs. Each CTA: 25 hidden units -> 100 gate rows.
// W_hh slice (100 rows x 400 cols) fully register-resident: 400 threads, each
// thread = (colseg 0..7 of 50 cols) x (row-pair 0..49), 100 weights/thread as
// float2 for fma.rn.f32x2 (packed fp32 FMA, 2x fp32 rate, exact).
// h exchange: 25 producer threads st.shared::cluster into all 16 peer CTAs'
// smem, then barrier.cluster. Double-buffered h by step parity.
#define CSZ 16
#define HPC 25          // hidden per CTA
#define SCTH 400        // threads

__device__ __forceinline__ unsigned smem_u32(const void* p) {
    unsigned a;
    asm("{ .reg .u64 t; cvta.to.shared.u64 t, %1; cvt.u32.u64 %0, t; }" : "=r"(a) : "l"(p));
    return a;
}

__global__ void __launch_bounds__(SCTH, 1) __cluster_dims__(CSZ, 1, 1)
scan_cl_k(float* __restrict__ outp,
          const float* __restrict__ projf, const float* __restrict__ projb,
          const float* __restrict__ whhf, const float* __restrict__ whhb,
          const float* __restrict__ h0, const float* __restrict__ c0, int layer)
{
    __shared__ float hs[2][HN];
    __shared__ float psum[100 * 9];
    __shared__ float gsum[100];

    int dir  = blockIdx.x >> 4;
    int rank = blockIdx.x & 15;
    int k0   = rank * HPC;
    int tid  = threadIdx.x;

    const float* whh  = dir ? whhb : whhf;
    const float* proj = dir ? projb : projf;

    // mapping: seg = column segment (50 cols), rp = row pair
    int seg = tid / 50;          // 0..7
    int rp  = tid % 50;          // 0..49
    int lr0 = rp * 2, lr1 = rp * 2 + 1;

    // load W_hh slice into registers as float2 pairs
    float2 w0p[25], w1p[25];
    {
        int g0 = lr0 / HPC, i0 = lr0 % HPC;
        int g1 = lr1 / HPC, i1 = lr1 % HPC;
        const float2* p0 = (const float2*)(whh + (size_t)(g0 * HN + k0 + i0) * HN + seg * 50);
        const float2* p1 = (const float2*)(whh + (size_t)(g1 * HN + k0 + i1) * HN + seg * 50);
#pragma unroll
        for (int c = 0; c < 25; ++c) { w0p[c] = p0[c]; w1p[c] = p1[c]; }
    }

    // reduce-thread row info (tid < 100)
    int growr = (tid / HPC) * HN + k0 + (tid % HPC);   // global gate-row for row tid

    // init h, c
    for (int i = tid; i < HN; i += SCTH) hs[0][i] = h0[(2 * layer + dir) * HN + i];
    float creg = 0.f;
    if (tid < HPC) creg = c0[(2 * layer + dir) * HN + k0 + tid];
    unsigned hdst0 = smem_u32(&hs[0][k0 + (tid < HPC ? tid : 0)]);
    unsigned hdst1 = smem_u32(&hs[1][k0 + (tid < HPC ? tid : 0)]);
    __syncthreads();

    for (int t = 0; t < SEQN; ++t) {
        int par = t & 1;
        int tt = dir ? (SEQN - 1 - t) : t;

        // prefetch proj for the reduce phase (hidden under the FMA phase)
        float pv = 0.f;
        if (tid < 100) pv = __ldg(&proj[(size_t)tt * G4 + growr]);

        // packed-fp32 GEMV on the register-resident weights
        unsigned long long a0 = 0ull, a1 = 0ull;   // f32x2 accumulators (init = {0,0})
        const float2* hp = (const float2*)&hs[par][seg * 50];
#pragma unroll
        for (int c = 0; c < 25; ++c) {
            float2 hv = hp[c];
            unsigned long long hb = *(const unsigned long long*)&hv;
            asm("fma.rn.f32x2 %0, %1, %2, %0;"
                : "+l"(a0) : "l"(*(const unsigned long long*)&w0p[c]), "l"(hb));
            asm("fma.rn.f32x2 %0, %1, %2, %0;"
                : "+l"(a1) : "l"(*(const unsigned long long*)&w1p[c]), "l"(hb));
        }
        float s0lo, s0hi, s1lo, s1hi;
        asm("mov.b64 {%0, %1}, %2;" : "=f"(s0lo), "=f"(s0hi) : "l"(a0));
        asm("mov.b64 {%0, %1}, %2;" : "=f"(s1lo), "=f"(s1hi) : "l"(a1));
        psum[lr0 * 9 + seg] = s0lo + s0hi;
        psum[lr1 * 9 + seg] = s1lo + s1hi;
        __syncthreads();

        // per-row reduce (+input projection, biases already folded into proj)
        if (tid < 100) {
            float s = pv;
#pragma unroll
            for (int k = 0; k < 8; ++k) s += psum[tid * 9 + k];
            gsum[tid] = s;
        }
        __syncthreads();

        // activations + broadcast h to all 16 CTAs via DSMEM
        if (tid < HPC) {
            float iv = gsum[tid];
            float fv = gsum[HPC + tid];
            float gv = gsum[2 * HPC + tid];
            float ov = gsum[3 * HPC + tid];
            float ig = 1.f / (1.f + expf(-iv));
            float fg = 1.f / (1.f + expf(-fv));
            float og = 1.f / (1.f + expf(-ov));
            float cn = fmaf(fg, creg, ig * tanhf(gv));
            creg = cn;
            float hn = og * tanhf(cn);
            unsigned dst = par ? hdst0 : hdst1;   // write the other parity buffer
#pragma unroll
            for (int p = 0; p < CSZ; ++p) {
                unsigned r;
                asm("mapa.shared::cluster.u32 %0, %1, %2;" : "=r"(r) : "r"(dst), "r"(p));
                asm volatile("st.shared::cluster.f32 [%0], %1;" :: "r"(r), "f"(hn));
            }
            outp[(size_t)tt * BI2 + dir * HN + k0 + tid] = hn;
        }

        asm volatile("barrier.cluster.arrive.aligned;" ::: "memory");
        asm volatile("barrier.cluster.wait.aligned;" ::: "memory");
    }
}

// ------------------------- pairwise scorer -------------------------
#define PKC 32

__global__ void __launch_bounds__(256) pairwise_k(float* __restrict__ out,
    const float* __restrict__ A, const float* __restrict__ Bm,
    const float* __restrict__ w2, const float* __restrict__ b2p)
{
    __shared__ float As[32][PKC + 1];
    __shared__ float Bs[32][PKC + 1];
    __shared__ float ws[PKC];
    int tid = threadIdx.x;
    int i0 = blockIdx.y * 32, j0 = blockIdx.x * 32;
    int tx = tid & 15, ty = tid >> 4;
    int lr = tid >> 3, seg = tid & 7;
    float acc[2][2] = {{0.f, 0.f}, {0.f, 0.f}};

    for (int kc = 0; kc < G4; kc += PKC) {
        __syncthreads();
        float4 av = *(const float4*)(A  + (size_t)(i0 + lr) * G4 + kc + seg * 4);
        float4 bv = *(const float4*)(Bm + (size_t)(j0 + lr) * G4 + kc + seg * 4);
        As[lr][seg * 4 + 0] = av.x; As[lr][seg * 4 + 1] = av.y;
        As[lr][seg * 4 + 2] = av.z; As[lr][seg * 4 + 3] = av.w;
        Bs[lr][seg * 4 + 0] = bv.x; Bs[lr][seg * 4 + 1] = bv.y;
        Bs[lr][seg * 4 + 2] = bv.z; Bs[lr][seg * 4 + 3] = bv.w;
        if (tid < PKC) ws[tid] = w2[kc + tid];
        __syncthreads();
#pragma unroll
        for (int kk = 0; kk < PKC; ++kk) {
            float a0 = As[ty * 2 + 0][kk];
            float a1 = As[ty * 2 + 1][kk];
            float b0 = Bs[tx * 2 + 0][kk];
            float b1 = Bs[tx * 2 + 1][kk];
            float wv = ws[kk];
            acc[0][0] = fmaf(fmaxf(a0 + b0, 0.f), wv, acc[0][0]);
            acc[0][1] = fmaf(fmaxf(a0 + b1, 0.f), wv, acc[0][1]);
            acc[1][0] = fmaf(fmaxf(a1 + b0, 0.f), wv, acc[1][0]);
            acc[1][1] = fmaf(fmaxf(a1 + b1, 0.f), wv, acc[1][1]);
        }
    }
    float b2v = b2p[0];
#pragma unroll
    for (int a = 0; a < 2; ++a)
#pragma unroll
        for (int b = 0; b < 2; ++b) {
            int i = i0 + ty * 2 + a;
            int j = j0 + tx * 2 + b;
            float v = acc[a][b] + b2v;
            if (i == j) v = 0.f;
            out[(size_t)(i + 1) * NOUT + (j + 1)] = v;
        }
}

// ------------------------- border (row 0 / col 0) -------------------------
__global__ void border_k(float* __restrict__ out) {
    int i = blockIdx.x * blockDim.x + threadIdx.x;
    if (i < NOUT) {
        out[i] = (i == 0) ? 1.f : 0.f;
        out[(size_t)i * NOUT] = (i == 0) ? 1.f : 0.f;
    }
}

// ------------------------- launch -------------------------
extern "C" void kernel_launch(void* const* d_in, const int* in_sizes, int n_in,
                              void* d_out, int out_size) {
    const int*   words   = (const int*)d_in[0];
    const int*   tags    = (const int*)d_in[1];
    const float* wemb    = (const float*)d_in[3];
    const float* temb    = (const float*)d_in[4];
    const float* h0      = (const float*)d_in[5];
    const float* c0      = (const float*)d_in[6];
    const float* w_ih_l0 = (const float*)d_in[7];
    const float* w_hh_l0 = (const float*)d_in[8];
    const float* b_ih_l0 = (const float*)d_in[9];
    const float* b_hh_l0 = (const float*)d_in[10];
    const float* w_ih_l0r= (const float*)d_in[11];
    const float* w_hh_l0r= (const float*)d_in[12];
    const float* b_ih_l0r= (const float*)d_in[13];
    const float* b_hh_l0r= (const float*)d_in[14];
    const float* w_ih_l1 = (const float*)d_in[15];
    const float* w_hh_l1 = (const float*)d_in[16];
    const float* b_ih_l1 = (const float*)d_in[17];
    const float* b_hh_l1 = (const float*)d_in[18];
    const float* w_ih_l1r= (const float*)d_in[19];
    const float* w_hh_l1r= (const float*)d_in[20];
    const float* b_ih_l1r= (const float*)d_in[21];
    const float* b_hh_l1r= (const float*)d_in[22];
    const float* mlp_w1  = (const float*)d_in[23];
    const float* mlp_b1  = (const float*)d_in[24];
    const float* mlp_w2  = (const float*)d_in[25];
    const float* mlp_b2  = (const float*)d_in[26];
    float* out = (float*)d_out;

    float *px, *ppf, *ppb, *po0, *phv, *pA, *pB;
    cudaGetSymbolAddress((void**)&px,  g_x);
    cudaGetSymbolAddress((void**)&ppf, g_projf);
    cudaGetSymbolAddress((void**)&ppb, g_projb);
    cudaGetSymbolAddress((void**)&po0, g_out0);
    cudaGetSymbolAddress((void**)&phv, g_hv);
    cudaGetSymbolAddress((void**)&pA,  g_A);
    cudaGetSymbolAddress((void**)&pB,  g_B);

    // allow 16-CTA (non-portable) clusters for the scan kernel
    cudaFuncSetAttribute(scan_cl_k, cudaFuncAttributeNonPortableClusterSizeAllowed, 1);

    dim3 gg(G4 / BN, SEQN / BM);   // (25, 5)

    embed_k<<<SEQN, 128>>>(words, tags, wemb, temb);

    // layer 0 input projections (+ both biases folded)
    gemm_tn<<<gg, 256>>>(ppf, px, w_ih_l0,  b_ih_l0,  b_hh_l0,  G4, HN, HN);
    gemm_tn<<<gg, 256>>>(ppb, px, w_ih_l0r, b_ih_l0r, b_hh_l0r, G4, HN, HN);
    scan_cl_k<<<2 * CSZ, SCTH>>>(po0, ppf, ppb, w_hh_l0, w_hh_l0r, h0, c0, 0);

    // layer 1
    gemm_tn<<<gg, 256>>>(ppf, po0, w_ih_l1,  b_ih_l1,  b_hh_l1,  G4, BI2, BI2);
    gemm_tn<<<gg, 256>>>(ppb, po0, w_ih_l1r, b_ih_l1r, b_hh_l1r, G4, BI2, BI2);
    scan_cl_k<<<2 * CSZ, SCTH>>>(phv, ppf, ppb, w_hh_l1, w_hh_l1r, h0, c0, 1);

    // MLP halves
    gemm_tn<<<gg, 256>>>(pA, phv, mlp_w1,       mlp_b1, nullptr, G4, BI2, G4);
    gemm_tn<<<gg, 256>>>(pB, phv, mlp_w1 + BI2, nullptr, nullptr, G4, BI2, G4);

    border_k<<<(NOUT + 255) / 256, 256>>>(out);
    pairwise_k<<<dim3(SEQN / 32, SEQN / 32), 256>>>(out, pA, pB, mlp_w2, mlp_b2);
}

// round 11
// speedup vs baseline: 2.8810x; 1.2977x over previous
#include <cuda_runtime.h>
#include <math.h>

#define SEQN 320
#define HN   400
#define G4   1600   // 4*H
#define BI2  800    // 2*H
#define NOUT 321

// ------------------------- scratch (device globals; no allocation) -------------------------
__device__ float g_x[SEQN * HN];        // embedded input  [320,400]
__device__ float g_projf[SEQN * G4];    // input projections (reused per layer)
__device__ float g_projb[SEQN * G4];
__device__ float g_out0[SEQN * BI2];    // layer0 bilstm output
__device__ float g_hv[SEQN * BI2];      // layer1 bilstm output
__device__ float g_A[SEQN * G4];        // hv @ w1a^T + b1
__device__ float g_B[SEQN * G4];        // hv @ w1b^T

// ------------------------- embed -------------------------
__global__ void embed_k(const int* __restrict__ words, const int* __restrict__ tags,
                        const float* __restrict__ wemb, const float* __restrict__ temb) {
    int t = blockIdx.x;
    int w = words[t], tg = tags[t];
    for (int d = threadIdx.x; d < 300; d += blockDim.x) g_x[t * HN + d] = wemb[w * 300 + d];
    for (int d = threadIdx.x; d < 100; d += blockDim.x) g_x[t * HN + 300 + d] = temb[tg * 100 + d];
}

// ------------------------- GEMM: C[M,N] = X[M,K] * W[N,K]^T + bias1 + bias2 -------------------------
#define BM 64
#define BN 64
#define BKK 16

__global__ void __launch_bounds__(256) gemm_tn(float* __restrict__ C,
    const float* __restrict__ X, const float* __restrict__ W,
    const float* __restrict__ bias1, const float* __restrict__ bias2,
    int N, int K, int ldw)
{
    __shared__ float Xs[BKK][BM + 4];
    __shared__ float Ws[BKK][BN + 4];
    int tid = threadIdx.x;
    int m0 = blockIdx.y * BM, n0 = blockIdx.x * BN;
    int lr = tid >> 2, seg = tid & 3;
    const float* xp = X + (size_t)(m0 + lr) * K + seg * 4;
    const float* wp = W + (size_t)(n0 + lr) * ldw + seg * 4;
    int ty = tid >> 4, tx = tid & 15;
    float acc[4][4];
#pragma unroll
    for (int i = 0; i < 4; ++i)
#pragma unroll
        for (int j = 0; j < 4; ++j) acc[i][j] = 0.f;

    int nt = K / BKK;
    float4 xa = *(const float4*)xp;
    float4 wa = *(const float4*)wp;
    for (int kt = 0; kt < nt; ++kt) {
        __syncthreads();
        Xs[seg * 4 + 0][lr] = xa.x; Xs[seg * 4 + 1][lr] = xa.y;
        Xs[seg * 4 + 2][lr] = xa.z; Xs[seg * 4 + 3][lr] = xa.w;
        Ws[seg * 4 + 0][lr] = wa.x; Ws[seg * 4 + 1][lr] = wa.y;
        Ws[seg * 4 + 2][lr] = wa.z; Ws[seg * 4 + 3][lr] = wa.w;
        __syncthreads();
        if (kt + 1 < nt) {
            xa = *(const float4*)(xp + (kt + 1) * BKK);
            wa = *(const float4*)(wp + (kt + 1) * BKK);
        }
#pragma unroll
        for (int kk = 0; kk < BKK; ++kk) {
            float4 a = *(const float4*)&Xs[kk][ty * 4];
            float4 b = *(const float4*)&Ws[kk][tx * 4];
            float av[4] = {a.x, a.y, a.z, a.w};
            float bv[4] = {b.x, b.y, b.z, b.w};
#pragma unroll
            for (int i = 0; i < 4; ++i)
#pragma unroll
                for (int j = 0; j < 4; ++j)
                    acc[i][j] = fmaf(av[i], bv[j], acc[i][j]);
        }
    }
    float bb[4] = {0.f, 0.f, 0.f, 0.f};
    if (bias1) {
#pragma unroll
        for (int j = 0; j < 4; ++j) bb[j] += bias1[n0 + tx * 4 + j];
    }
    if (bias2) {
#pragma unroll
        for (int j = 0; j < 4; ++j) bb[j] += bias2[n0 + tx * 4 + j];
    }
#pragma unroll
    for (int i = 0; i < 4; ++i) {
        float4 o;
        o.x = acc[i][0] + bb[0]; o.y = acc[i][1] + bb[1];
        o.z = acc[i][2] + bb[2]; o.w = acc[i][3] + bb[3];
        *(float4*)(C + (size_t)(m0 + ty * 4 + i) * N + n0 + tx * 4) = o;
    }
}

// ------------------------- recurrent scan: cluster + st.async mbarrier sync -------------------------
// 2 clusters (fwd, bwd) of 16 CTAs. Each CTA: 25 hidden units -> 100 gate rows,
// W_hh slice (100x400) register-resident, fma.rn.f32x2 GEMV.
// Per-step sync: producers push h via st.async.shared::cluster with
// mbarrier::complete_tx (1600 B expected per CTA per step); consumers
// try_wait on a depth-4 ring of (buffer, mbarrier) pairs. No cluster barrier
// in the loop.
#define CSZ 16
#define HPC 25          // hidden per CTA
#define SCTH 400        // threads

__device__ __forceinline__ unsigned smem_u32(const void* p) {
    unsigned a;
    asm("{ .reg .u64 t; cvta.to.shared.u64 t, %1; cvt.u32.u64 %0, t; }" : "=r"(a) : "l"(p));
    return a;
}

__device__ __forceinline__ void mbar_wait_cluster(unsigned mbar, unsigned parity) {
    unsigned done;
    asm volatile(
        "{\n\t.reg .pred p;\n\t"
        "mbarrier.try_wait.parity.acquire.cluster.shared::cta.b64 p, [%1], %2;\n\t"
        "selp.b32 %0, 1, 0, p;\n\t}"
        : "=r"(done) : "r"(mbar), "r"(parity) : "memory");
    if (!done) {
        asm volatile(
            "{\n\t.reg .pred P1;\n\t"
            "WL_%=:\n\t"
            "mbarrier.try_wait.parity.acquire.cluster.shared::cta.b64 P1, [%0], %1, 0x989680;\n\t"
            "@P1 bra.uni WD_%=;\n\t"
            "bra.uni WL_%=;\n\t"
            "WD_%=:\n\t}"
            :: "r"(mbar), "r"(parity) : "memory");
    }
}

__device__ __forceinline__ float sig_f(float x) {
    return __fdividef(1.f, 1.f + __expf(-x));
}
__device__ __forceinline__ float tanh_f(float x) {
    // 1 - 2/(e^{2x}+1): saturates correctly for |x| large
    return 1.f - __fdividef(2.f, __expf(2.f * x) + 1.f);
}

__global__ void __launch_bounds__(SCTH, 1) __cluster_dims__(CSZ, 1, 1)
scan_cl_k(float* __restrict__ outp,
          const float* __restrict__ projf, const float* __restrict__ projb,
          const float* __restrict__ whhf, const float* __restrict__ whhb,
          const float* __restrict__ h0, const float* __restrict__ c0, int layer)
{
    __shared__ float hs[4][HN];                 // depth-4 h ring
    __shared__ float psum[100 * 9];
    __shared__ unsigned long long mb[4];        // one mbarrier per ring slot

    int dir  = blockIdx.x >> 4;
    int rank = blockIdx.x & 15;
    int k0   = rank * HPC;
    int tid  = threadIdx.x;

    const float* whh  = dir ? whhb : whhf;
    const float* proj = dir ? projb : projf;

    // FMA mapping: seg = 50-col segment (0..7), rp = row pair (0..49)
    int seg = tid / 50;
    int rp  = tid % 50;
    int lr0 = rp * 2, lr1 = rp * 2 + 1;

    float2 w0p[25], w1p[25];
    {
        int g0 = lr0 / HPC, i0 = lr0 % HPC;
        int g1 = lr1 / HPC, i1 = lr1 % HPC;
        const float2* p0 = (const float2*)(whh + (size_t)(g0 * HN + k0 + i0) * HN + seg * 50);
        const float2* p1 = (const float2*)(whh + (size_t)(g1 * HN + k0 + i1) * HN + seg * 50);
#pragma unroll
        for (int c = 0; c < 25; ++c) { w0p[c] = p0[c]; w1p[c] = p1[c]; }
    }

    // init: local h0 copy, c0, mbarriers
    for (int i = tid; i < HN; i += SCTH) hs[0][i] = h0[(2 * layer + dir) * HN + i];
    float creg = (tid < HPC) ? c0[(2 * layer + dir) * HN + k0 + tid] : 0.f;
    if (tid == 0) {
#pragma unroll
        for (int b = 0; b < 4; ++b)
            asm volatile("mbarrier.init.shared.b64 [%0], %1;"
                         :: "r"(smem_u32(&mb[b])), "r"(1u) : "memory");
        asm volatile("fence.mbarrier_init.release.cluster;" ::: "memory");
    }
    __syncthreads();
    // one-time cluster barrier: peers' mbarrier init must be visible before st.async
    asm volatile("barrier.cluster.arrive.aligned;" ::: "memory");
    asm volatile("barrier.cluster.wait.aligned;" ::: "memory");

    bool actl = (tid < HPC);
    unsigned mb_local[4];
    unsigned hb_local[4];
#pragma unroll
    for (int b = 0; b < 4; ++b) {
        mb_local[b] = smem_u32(&mb[b]);
        hb_local[b] = smem_u32(&hs[b][k0 + (actl ? tid : 0)]);
    }
    unsigned mb0 = smem_u32(&mb[0]);

    for (int u = 0; u < 80; ++u) {
        unsigned pr = (unsigned)(u & 1);
#pragma unroll
        for (int q = 0; q < 4; ++q) {
            int t  = 4 * u + q;
            int cb = q;
            int nb = (q + 1) & 3;

            // wait for ring slot cb to be filled (skip t=0: pre-filled locally)
            if (q != 0) {
                mbar_wait_cluster(mb_local[cb], pr);
            } else if (u != 0) {
                mbar_wait_cluster(mb_local[0], pr ^ 1u);
            }
            // arm the next slot's mbarrier (1 arrive + 1600 tx bytes)
            if (tid == 0 && t < SEQN - 1) {
                asm volatile("mbarrier.arrive.expect_tx.shared.b64 _, [%0], %1;"
                             :: "r"(mb_local[nb]), "r"(1600u) : "memory");
            }

            int tt = dir ? (SEQN - 1 - t) : t;

            // proj prefetch for act lanes (covered by the FMA phase)
            float pv0 = 0.f, pv1 = 0.f, pv2 = 0.f, pv3 = 0.f;
            if (actl) {
                const float* pp = proj + (size_t)tt * G4 + k0 + tid;
                pv0 = __ldg(pp);
                pv1 = __ldg(pp + HN);
                pv2 = __ldg(pp + 2 * HN);
                pv3 = __ldg(pp + 3 * HN);
            }

            // packed-fp32 GEMV on register-resident weights
            unsigned long long a0 = 0ull, a1 = 0ull;
            const float2* hp = (const float2*)&hs[cb][seg * 50];
#pragma unroll
            for (int c = 0; c < 25; ++c) {
                float2 hv = hp[c];
                unsigned long long hbb = *(const unsigned long long*)&hv;
                asm("fma.rn.f32x2 %0, %1, %2, %0;"
                    : "+l"(a0) : "l"(*(const unsigned long long*)&w0p[c]), "l"(hbb));
                asm("fma.rn.f32x2 %0, %1, %2, %0;"
                    : "+l"(a1) : "l"(*(const unsigned long long*)&w1p[c]), "l"(hbb));
            }
            float s0lo, s0hi, s1lo, s1hi;
            asm("mov.b64 {%0, %1}, %2;" : "=f"(s0lo), "=f"(s0hi) : "l"(a0));
            asm("mov.b64 {%0, %1}, %2;" : "=f"(s1lo), "=f"(s1hi) : "l"(a1));
            psum[lr0 * 9 + seg] = s0lo + s0hi;
            psum[lr1 * 9 + seg] = s1lo + s1hi;
            __syncthreads();

            // fused reduce + activations + DSMEM broadcast (25 lanes of warp 0)
            if (actl) {
                float gi = pv0, gf = pv1, gg = pv2, go = pv3;
#pragma unroll
                for (int k = 0; k < 8; ++k) {
                    gi += psum[(tid)      * 9 + k];
                    gf += psum[(25 + tid) * 9 + k];
                    gg += psum[(50 + tid) * 9 + k];
                    go += psum[(75 + tid) * 9 + k];
                }
                float ig = sig_f(gi);
                float fg = sig_f(gf);
                float og = sig_f(go);
                float cn = fmaf(fg, creg, ig * tanh_f(gg));
                creg = cn;
                float hn = og * tanh_f(cn);
                outp[(size_t)tt * BI2 + dir * HN + k0 + tid] = hn;
                if (t < SEQN - 1) {
                    unsigned uv = __float_as_uint(hn);
                    unsigned hb = hb_local[nb];
                    unsigned mbb = mb_local[nb];
#pragma unroll
                    for (int p = 0; p < CSZ; ++p) {
                        unsigned ra, rm;
                        asm("mapa.shared::cluster.u32 %0, %1, %2;" : "=r"(ra) : "r"(hb),  "r"(p));
                        asm("mapa.shared::cluster.u32 %0, %1, %2;" : "=r"(rm) : "r"(mbb), "r"(p));
                        asm volatile(
                            "st.async.shared::cluster.mbarrier::complete_tx::bytes.u32 [%0], %1, [%2];"
                            :: "r"(ra), "r"(uv), "r"(rm) : "memory");
                    }
                }
            }
            // no second __syncthreads: next-step mbarrier wait gates hs reads,
            // and mb[nb] cannot complete before our act warp finished psum reads.
        }
    }
    (void)mb0;
}

// ------------------------- pairwise scorer -------------------------
#define PKC 32

__global__ void __launch_bounds__(256) pairwise_k(float* __restrict__ out,
    const float* __restrict__ A, const float* __restrict__ Bm,
    const float* __restrict__ w2, const float* __restrict__ b2p)
{
    __shared__ float As[32][PKC + 1];
    __shared__ float Bs[32][PKC + 1];
    __shared__ float ws[PKC];
    int tid = threadIdx.x;
    int i0 = blockIdx.y * 32, j0 = blockIdx.x * 32;
    int tx = tid & 15, ty = tid >> 4;
    int lr = tid >> 3, seg = tid & 7;
    float acc[2][2] = {{0.f, 0.f}, {0.f, 0.f}};

    for (int kc = 0; kc < G4; kc += PKC) {
        __syncthreads();
        float4 av = *(const float4*)(A  + (size_t)(i0 + lr) * G4 + kc + seg * 4);
        float4 bv = *(const float4*)(Bm + (size_t)(j0 + lr) * G4 + kc + seg * 4);
        As[lr][seg * 4 + 0] = av.x; As[lr][seg * 4 + 1] = av.y;
        As[lr][seg * 4 + 2] = av.z; As[lr][seg * 4 + 3] = av.w;
        Bs[lr][seg * 4 + 0] = bv.x; Bs[lr][seg * 4 + 1] = bv.y;
        Bs[lr][seg * 4 + 2] = bv.z; Bs[lr][seg * 4 + 3] = bv.w;
        if (tid < PKC) ws[tid] = w2[kc + tid];
        __syncthreads();
#pragma unroll
        for (int kk = 0; kk < PKC; ++kk) {
            float a0 = As[ty * 2 + 0][kk];
            float a1 = As[ty * 2 + 1][kk];
            float b0 = Bs[tx * 2 + 0][kk];
            float b1 = Bs[tx * 2 + 1][kk];
            float wv = ws[kk];
            acc[0][0] = fmaf(fmaxf(a0 + b0, 0.f), wv, acc[0][0]);
            acc[0][1] = fmaf(fmaxf(a0 + b1, 0.f), wv, acc[0][1]);
            acc[1][0] = fmaf(fmaxf(a1 + b0, 0.f), wv, acc[1][0]);
            acc[1][1] = fmaf(fmaxf(a1 + b1, 0.f), wv, acc[1][1]);
        }
    }
    float b2v = b2p[0];
#pragma unroll
    for (int a = 0; a < 2; ++a)
#pragma unroll
        for (int b = 0; b < 2; ++b) {
            int i = i0 + ty * 2 + a;
            int j = j0 + tx * 2 + b;
            float v = acc[a][b] + b2v;
            if (i == j) v = 0.f;
            out[(size_t)(i + 1) * NOUT + (j + 1)] = v;
        }
}

// ------------------------- border (row 0 / col 0) -------------------------
__global__ void border_k(float* __restrict__ out) {
    int i = blockIdx.x * blockDim.x + threadIdx.x;
    if (i < NOUT) {
        out[i] = (i == 0) ? 1.f : 0.f;
        out[(size_t)i * NOUT] = (i == 0) ? 1.f : 0.f;
    }
}

// ------------------------- launch -------------------------
extern "C" void kernel_launch(void* const* d_in, const int* in_sizes, int n_in,
                              void* d_out, int out_size) {
    const int*   words   = (const int*)d_in[0];
    const int*   tags    = (const int*)d_in[1];
    const float* wemb    = (const float*)d_in[3];
    const float* temb    = (const float*)d_in[4];
    const float* h0      = (const float*)d_in[5];
    const float* c0      = (const float*)d_in[6];
    const float* w_ih_l0 = (const float*)d_in[7];
    const float* w_hh_l0 = (const float*)d_in[8];
    const float* b_ih_l0 = (const float*)d_in[9];
    const float* b_hh_l0 = (const float*)d_in[10];
    const float* w_ih_l0r= (const float*)d_in[11];
    const float* w_hh_l0r= (const float*)d_in[12];
    const float* b_ih_l0r= (const float*)d_in[13];
    const float* b_hh_l0r= (const float*)d_in[14];
    const float* w_ih_l1 = (const float*)d_in[15];
    const float* w_hh_l1 = (const float*)d_in[16];
    const float* b_ih_l1 = (const float*)d_in[17];
    const float* b_hh_l1 = (const float*)d_in[18];
    const float* w_ih_l1r= (const float*)d_in[19];
    const float* w_hh_l1r= (const float*)d_in[20];
    const float* b_ih_l1r= (const float*)d_in[21];
    const float* b_hh_l1r= (const float*)d_in[22];
    const float* mlp_w1  = (const float*)d_in[23];
    const float* mlp_b1  = (const float*)d_in[24];
    const float* mlp_w2  = (const float*)d_in[25];
    const float* mlp_b2  = (const float*)d_in[26];
    float* out = (float*)d_out;

    float *px, *ppf, *ppb, *po0, *phv, *pA, *pB;
    cudaGetSymbolAddress((void**)&px,  g_x);
    cudaGetSymbolAddress((void**)&ppf, g_projf);
    cudaGetSymbolAddress((void**)&ppb, g_projb);
    cudaGetSymbolAddress((void**)&po0, g_out0);
    cudaGetSymbolAddress((void**)&phv, g_hv);
    cudaGetSymbolAddress((void**)&pA,  g_A);
    cudaGetSymbolAddress((void**)&pB,  g_B);

    // allow 16-CTA (non-portable) clusters for the scan kernel
    cudaFuncSetAttribute(scan_cl_k, cudaFuncAttributeNonPortableClusterSizeAllowed, 1);

    dim3 gg(G4 / BN, SEQN / BM);   // (25, 5)

    embed_k<<<SEQN, 128>>>(words, tags, wemb, temb);

    // layer 0 input projections (+ both biases folded)
    gemm_tn<<<gg, 256>>>(ppf, px, w_ih_l0,  b_ih_l0,  b_hh_l0,  G4, HN, HN);
    gemm_tn<<<gg, 256>>>(ppb, px, w_ih_l0r, b_ih_l0r, b_hh_l0r, G4, HN, HN);
    scan_cl_k<<<2 * CSZ, SCTH>>>(po0, ppf, ppb, w_hh_l0, w_hh_l0r, h0, c0, 0);

    // layer 1
    gemm_tn<<<gg, 256>>>(ppf, po0, w_ih_l1,  b_ih_l1,  b_hh_l1,  G4, BI2, BI2);
    gemm_tn<<<gg, 256>>>(ppb, po0, w_ih_l1r, b_ih_l1r, b_hh_l1r, G4, BI2, BI2);
    scan_cl_k<<<2 * CSZ, SCTH>>>(phv, ppf, ppb, w_hh_l1, w_hh_l1r, h0, c0, 1);

    // MLP halves
    gemm_tn<<<gg, 256>>>(pA, phv, mlp_w1,       mlp_b1, nullptr, G4, BI2, G4);
    gemm_tn<<<gg, 256>>>(pB, phv, mlp_w1 + BI2, nullptr, nullptr, G4, BI2, G4);

    border_k<<<(NOUT + 255) / 256, 256>>>(out);
    pairwise_k<<<dim3(SEQN / 32, SEQN / 32), 256>>>(out, pA, pB, mlp_w2, mlp_b2);
}